// round 16
// baseline (speedup 1.0000x reference)
#include <cuda_runtime.h>
#include <math.h>

#define BATCH 16
#define H     1024
#define W     1024
#define HS    512
#define WS    512
#define HC    256
#define WC    256
#define C1    32
#define KP    32
#define CROPSZ 160
#define NSL   32
#define SLICE 2048

// fused conv tile params
#define FTX 64
#define FTY 16
#define IMGW 144
#define SH1W 72
#define SH1SZ (20 * SH1W)

// ---- scratch (static __device__ per allocation rules) ----
__device__ float g_img[BATCH * HS * WS];             // 16 MB: resized 512x512
__device__ float g_cms[BATCH * HC * WC];             // 4 MB: confmaps
__device__ float g_nms[BATCH * HC * WC];             // 4 MB
__device__ unsigned long long g_pkey[BATCH * NSL * KP]; // per-slice top-32 keys
__device__ float g_cx[BATCH * KP];
__device__ float g_cy[BATCH * KP];
__device__ int   g_vld[BATCH * KP];

// output layout (flat concat, f32): crops | crop_offsets | centroid_vals | valid
#define OFF_OFFS  (BATCH * KP * CROPSZ * CROPSZ)
#define OFF_VALS  (OFF_OFFS + BATCH * KP * 2)
#define OFF_VALID (OFF_VALS + BATCH * KP)

// ============================================================
// 1) antialiased bilinear x0.5 resize — single pass, row-block.
// ============================================================
__global__ void __launch_bounds__(256) k_resize2(const float* __restrict__ in) {
    __shared__ float sht[18][512];
    int tid = threadIdx.x;
    int Y0  = blockIdx.x * 8;
    int b   = blockIdx.y;
    const float* ip = in + (size_t)b * H * W;
    int gy0 = 2 * Y0 - 1;

    for (int e = tid; e < 18 * 512; e += 256) {
        int r  = e >> 9;
        int xo = e & 511;
        int gy = gy0 + r;
        float v = 0.f;
        if (gy >= 0 && gy < H) {
            const float* row = ip + (size_t)gy * W;
            int base = 2 * xo - 1;
            float acc = 0.75f * row[base + 1] + 0.75f * row[base + 2];
            float wsum = 1.5f;
            if (base >= 0)    { acc += 0.25f * row[base];     wsum += 0.25f; }
            if (base + 3 < W) { acc += 0.25f * row[base + 3]; wsum += 0.25f; }
            v = acc / wsum;
        }
        sht[r][xo] = v;
    }
    __syncthreads();

    float* op = g_img + (size_t)b * HS * WS;
    for (int e = tid; e < 8 * 512; e += 256) {
        int yo = e >> 9;
        int xo = e & 511;
        int Y  = Y0 + yo;
        int lr = 2 * yo;
        float acc = 0.25f * sht[lr][xo]     + 0.75f * sht[lr + 1][xo]
                  + 0.75f * sht[lr + 2][xo] + 0.25f * sht[lr + 3][xo];
        float wsum = 2.f - 0.25f * ((Y == 0) + (Y == 511));
        op[(size_t)Y * WS + xo] = acc / wsum;
    }
}

// ============================================================
// 2) FUSED conv1 + conv2
// ============================================================
__device__ __forceinline__ unsigned long long pack2(float a, float b) {
    unsigned long long r;
    asm("mov.b64 %0, {%1, %2};" : "=l"(r) : "r"(__float_as_uint(a)), "r"(__float_as_uint(b)));
    return r;
}
__device__ __forceinline__ void unpack2(unsigned long long v, float& a, float& b) {
    unsigned int lo, hi;
    asm("mov.b64 {%0, %1}, %2;" : "=r"(lo), "=r"(hi) : "l"(v));
    a = __uint_as_float(lo); b = __uint_as_float(hi);
}
__device__ __forceinline__ void ffma2(unsigned long long& acc,
                                      unsigned long long v, unsigned long long w) {
    asm("fma.rn.f32x2 %0, %1, %2, %3;" : "=l"(acc) : "l"(v), "l"(w), "l"(acc));
}

#define SMEM_FUSED (400*8 + 32*4 + 800*4 + 43*IMGW*4 + 4*SH1SZ*4)

__global__ void __launch_bounds__(256) k_fused(const float* __restrict__ w1,
                                               const float* __restrict__ b1,
                                               const float* __restrict__ w2,
                                               const float* __restrict__ b2) {
    extern __shared__ unsigned char smraw[];
    unsigned long long* swp = (unsigned long long*)smraw;
    float* sbias = (float*)(swp + 400);
    float* sw2   = sbias + 32;
    float* simg  = sw2 + 800;
    float* sh1   = simg + 43 * IMGW;

    int tid  = threadIdx.x;
    int lane = tid & 31, wrow = tid >> 5;
    int x0 = blockIdx.x * FTX, y0 = blockIdx.y * FTY, b = blockIdx.z;

    if (tid < 200) {
        swp[tid]       = ((const unsigned long long*)w1)[tid];
        swp[200 + tid] = ((const unsigned long long*)w1)[200 + tid];
    }
    if (tid < 32) sbias[tid] = b1[tid];
    for (int e = tid; e < 800; e += 256) {
        int c = e / 25, t = e - c * 25;
        sw2[e] = w2[t * C1 + c];
    }

    const float* ip = g_img + (size_t)b * HS * WS;
    int iy0 = 2 * y0 - 5, ix0 = 2 * x0 - 5;
    for (int ly = wrow; ly < 43; ly += 8) {
        int gy = iy0 + ly;
        bool rok = (gy >= 0 && gy < HS);
        const float* prow = ip + (size_t)gy * WS;
        #pragma unroll
        for (int xc = 0; xc < 5; xc++) {
            int lx = lane + 32 * xc;
            if (xc == 4 && lane >= 11) continue;
            int gx = ix0 + lx;
            float v = 0.f;
            if (rok && gx >= 0 && gx < WS) v = prow[gx];
            simg[ly * IMGW + lx] = v;
        }
    }
    __syncthreads();

    int tx = tid & 15;
    int ty = tid >> 4;
    float acc2[4] = {0.f, 0.f, 0.f, 0.f};

    for (int cb = 0; cb < 8; cb++) {
        if (cb) __syncthreads();

        for (int e = tid; e < 20 * 68; e += 256) {
            int row = e / 68, col = e - row * 68;
            bool inb = ((unsigned)(y0 - 2 + row) < HC) &&
                       ((unsigned)(x0 - 2 + col) < WC);
            const float* pb = simg + (2 * row) * IMGW + 2 * col;
            float iv[25];
            #pragma unroll
            for (int ky = 0; ky < 5; ky++) {
                const float2* p2 = (const float2*)(pb + ky * IMGW);
                float2 a01 = p2[0];
                float2 a23 = p2[1];
                float  a4  = pb[ky * IMGW + 4];
                iv[ky * 5 + 0] = a01.x;
                iv[ky * 5 + 1] = a01.y;
                iv[ky * 5 + 2] = a23.x;
                iv[ky * 5 + 3] = a23.y;
                iv[ky * 5 + 4] = a4;
            }

            unsigned long long acc[2];
            #pragma unroll
            for (int j = 0; j < 2; j++)
                acc[j] = pack2(sbias[cb * 4 + 2 * j], sbias[cb * 4 + 2 * j + 1]);
            #pragma unroll
            for (int t = 0; t < 25; t++) {
                unsigned long long vv = pack2(iv[t], iv[t]);
                #pragma unroll
                for (int j = 0; j < 2; j++)
                    ffma2(acc[j], vv, swp[t * 16 + cb * 2 + j]);
            }
            int base = row * SH1W + col;
            #pragma unroll
            for (int j = 0; j < 2; j++) {
                float a, c2;
                unpack2(acc[j], a, c2);
                a  = inb ? fmaxf(a, 0.f)  : 0.f;
                c2 = inb ? fmaxf(c2, 0.f) : 0.f;
                sh1[(2 * j)     * SH1SZ + base] = a;
                sh1[(2 * j + 1) * SH1SZ + base] = c2;
            }
        }
        __syncthreads();

        #pragma unroll
        for (int c = 0; c < 4; c++) {
            const float* wp = sw2 + (cb * 4 + c) * 25;
            float wr[25];
            #pragma unroll
            for (int t = 0; t < 25; t++) wr[t] = wp[t];
            #pragma unroll
            for (int r = 0; r < 5; r++) {
                const float4* rp = (const float4*)(sh1 + c * SH1SZ + (ty + r) * SH1W);
                float4 va = rp[tx];
                float4 vb = rp[tx + 1];
                float v[8] = {va.x, va.y, va.z, va.w, vb.x, vb.y, vb.z, vb.w};
                #pragma unroll
                for (int kx = 0; kx < 5; kx++) {
                    float w = wr[r * 5 + kx];
                    #pragma unroll
                    for (int ox = 0; ox < 4; ox++)
                        acc2[ox] = fmaf(v[ox + kx], w, acc2[ox]);
                }
            }
        }
    }

    float bias2 = __ldg(b2);
    int gy = y0 + ty;
    #pragma unroll
    for (int ox = 0; ox < 4; ox++) {
        int gx = x0 + tx * 4 + ox;
        float z = acc2[ox] + bias2;
        g_cms[((size_t)b * HC + gy) * WC + gx] = 1.f / (1.f + expf(-z));
    }
}

// ============================================================
// 4a) 3x3 NMS + threshold -> global score buffer
// ============================================================
__global__ void __launch_bounds__(256) k_nms() {
    int i = blockIdx.x * blockDim.x + threadIdx.x;
    if (i >= BATCH * HC * WC) return;
    int p = i & (HC * WC - 1);
    int b = i >> 16;
    int y = p >> 8, x = p & 255;
    const float* cm = g_cms + (size_t)b * HC * WC;
    float v = cm[p];
    float mx = v;
    #pragma unroll
    for (int dy = -1; dy <= 1; dy++) {
        int yy = y + dy;
        if (yy < 0 || yy >= HC) continue;
        #pragma unroll
        for (int dx = -1; dx <= 1; dx++) {
            int xx = x + dx;
            if (xx < 0 || xx >= WC) continue;
            mx = fmaxf(mx, cm[yy * WC + xx]);
        }
    }
    g_nms[i] = (v >= mx && v > 0.2f) ? v : -INFINITY;
}

// ============================================================
// 4b) top-32 stage A: one WARP per 2048-elem slice, no block barriers
// ============================================================
__device__ __forceinline__ unsigned int f2ord(float v) {
    unsigned int u = __float_as_uint(v);
    return (u & 0x80000000u) ? ~u : (u | 0x80000000u);
}
__device__ __forceinline__ float ord2f(unsigned int u) {
    unsigned int bits = (u & 0x80000000u) ? (u ^ 0x80000000u) : ~u;
    return __uint_as_float(bits);
}
__device__ __forceinline__ unsigned long long mk_key(float v, unsigned p) {
    return ((unsigned long long)f2ord(v) << 32) |
           (unsigned long long)(0xFFFFFFFFu - p);
}

__global__ void __launch_bounds__(256) k_topk_part() {
    int wid  = threadIdx.x >> 5;            // warp in block: 0..7
    int lane = threadIdx.x & 31;
    int sl   = blockIdx.x * 8 + wid;        // slice 0..31
    int b    = blockIdx.y;
    float* nms = g_nms + (size_t)b * HC * WC;
    unsigned base = sl * SLICE;

    // lane owns elements base + s*32 + lane, s=0..63
    unsigned long long mybest = 0;
    #pragma unroll 8
    for (int s = 0; s < 64; s++) {
        unsigned p = base + s * 32 + lane;
        unsigned long long key = mk_key(nms[p], p);
        if (key > mybest) mybest = key;
    }

    unsigned long long* outk = g_pkey + (b * NSL + sl) * KP;

    for (int k = 0; k < KP; k++) {
        unsigned long long v = mybest;
        #pragma unroll
        for (int off = 16; off > 0; off >>= 1) {
            unsigned long long o = __shfl_xor_sync(0xFFFFFFFFu, v, off);
            if (o > v) v = o;
        }
        if (lane == 0) outk[k] = v;
        unsigned int widx = 0xFFFFFFFFu - (unsigned int)(v & 0xFFFFFFFFu);
        if ((widx & 31u) == (unsigned)lane) {   // owner removes + rescans
            nms[widx] = -INFINITY;
            unsigned long long nb = 0;
            #pragma unroll 8
            for (int s = 0; s < 64; s++) {
                unsigned p = base + s * 32 + lane;
                unsigned long long key = mk_key(nms[p], p);
                if (key > nb) nb = key;
            }
            mybest = nb;
        }
        __syncwarp();
    }
}

// ============================================================
// 4c) top-32 stage B: warp merge of 32x32 candidates + refine
// ============================================================
__global__ void __launch_bounds__(32) k_topk_merge(float* __restrict__ out) {
    int b    = blockIdx.x;
    int lane = threadIdx.x;         // 0..31

    // lane holds slot `lane` of each of the 32 slices (registers)
    unsigned long long cand[NSL];
    #pragma unroll
    for (int j = 0; j < NSL; j++)
        cand[j] = g_pkey[(b * NSL + j) * KP + lane];

    unsigned long long mybest = 0;
    #pragma unroll
    for (int j = 0; j < NSL; j++)
        if (cand[j] > mybest) mybest = cand[j];

    unsigned long long mywin = 0;
    for (int k = 0; k < KP; k++) {
        unsigned long long v = mybest;
        #pragma unroll
        for (int off = 16; off > 0; off >>= 1) {
            unsigned long long o = __shfl_xor_sync(0xFFFFFFFFu, v, off);
            if (o > v) v = o;
        }
        if (lane == k) mywin = v;
        if (mybest == v) {           // owner removes (keys unique)
            unsigned long long nb = 0;
            #pragma unroll
            for (int j = 0; j < NSL; j++) {
                if (cand[j] == v) cand[j] = 0;
                if (cand[j] > nb) nb = cand[j];
            }
            mybest = nb;
        }
    }

    // refine: lane k handles peak k
    int i = b * KP + lane;
    float vv = ord2f((unsigned int)(mywin >> 32));
    unsigned idx = 0xFFFFFFFFu - (unsigned int)(mywin & 0xFFFFFFFFu);
    int valid = isfinite(vv) ? 1 : 0;
    int py = (int)(idx >> 8), px = (int)(idx & 255);
    const float* cm = g_cms + (size_t)b * HC * WC;

    float gv = 1e-12f, sx = 0.f, sy = 0.f;
    #pragma unroll
    for (int dy = -2; dy <= 2; dy++) {
        int y = py + dy;
        if (y < 0 || y >= HC) continue;
        #pragma unroll
        for (int dx = -2; dx <= 2; dx++) {
            int x = px + dx;
            if (x < 0 || x >= WC) continue;
            float p = cm[y * WC + x];
            gv += p;
            sx += p * (float)dx;
            sy += p * (float)dy;
        }
    }
    float dxo = sx / gv, dyo = sy / gv;
    float cx = ((float)px + dxo) * 4.0f;
    float cy = ((float)py + dyo) * 4.0f;
    if (!valid) { cx = 80.f; cy = 80.f; }
    float cvv = valid ? vv : 0.f;

    g_cx[i] = cx; g_cy[i] = cy; g_vld[i] = valid;
    out[OFF_OFFS + i * 2 + 0] = cx - 80.f;
    out[OFF_OFFS + i * 2 + 1] = cy - 80.f;
    out[OFF_VALS + i] = cvv;
    out[OFF_VALID + i] = valid ? 1.f : 0.f;
}

// ============================================================
// 6) 160x160 bilinear crops: 4 outputs/thread, interior fast path
// ============================================================
__global__ void __launch_bounds__(256) k_crop(const float* __restrict__ img,
                                              float* __restrict__ out) {
    int bk = blockIdx.y;
    int q  = blockIdx.x * blockDim.x + threadIdx.x;
    if (q >= CROPSZ * CROPSZ / 4) return;
    float4* o = (float4*)(out + (size_t)bk * CROPSZ * CROPSZ) + q;
    if (!g_vld[bk]) { *o = make_float4(0.f, 0.f, 0.f, 0.f); return; }

    int b = bk / KP;
    float cx = g_cx[bk], cy = g_cy[bk];
    int pix = q * 4;
    int yy = pix / CROPSZ, xxb = pix % CROPSZ;

    float syf = cy - 79.5f + (float)yy;
    float y0 = floorf(syf);
    float wy = syf - y0;
    int iy0 = min(max((int)y0, 0), H - 1);
    int iy1 = min(max((int)y0 + 1, 0), H - 1);
    bool rowin = (syf >= 0.f) && (syf <= (float)(H - 1));
    const float* r0 = img + (size_t)b * H * W + (size_t)iy0 * W;
    const float* r1 = img + (size_t)b * H * W + (size_t)iy1 * W;

    float sxf0 = cx - 79.5f + (float)xxb;
    float x0f  = floorf(sxf0);
    float wx   = sxf0 - x0f;
    int x0i    = (int)x0f;

    float res[4];
    if (rowin && x0i >= 0 && x0i <= W - 5) {
        float c0 = __ldg(&r0[x0i]),     c1 = __ldg(&r0[x0i + 1]);
        float c2 = __ldg(&r0[x0i + 2]), c3 = __ldg(&r0[x0i + 3]);
        float c4 = __ldg(&r0[x0i + 4]);
        float d0 = __ldg(&r1[x0i]),     d1 = __ldg(&r1[x0i + 1]);
        float d2 = __ldg(&r1[x0i + 2]), d3 = __ldg(&r1[x0i + 3]);
        float d4 = __ldg(&r1[x0i + 4]);
        float iwx = 1.f - wx, iwy = 1.f - wy;
        float t0 = c0 * iwx + c1 * wx, t1 = c1 * iwx + c2 * wx;
        float t2 = c2 * iwx + c3 * wx, t3 = c3 * iwx + c4 * wx;
        float u0 = d0 * iwx + d1 * wx, u1 = d1 * iwx + d2 * wx;
        float u2 = d2 * iwx + d3 * wx, u3 = d3 * iwx + d4 * wx;
        res[0] = t0 * iwy + u0 * wy;
        res[1] = t1 * iwy + u1 * wy;
        res[2] = t2 * iwy + u2 * wy;
        res[3] = t3 * iwy + u3 * wy;
    } else {
        #pragma unroll
        for (int ox = 0; ox < 4; ox++) {
            float sxf = cx - 79.5f + (float)(xxb + ox);
            float x0 = floorf(sxf);
            float wxs = sxf - x0;
            int ix0 = min(max((int)x0, 0), W - 1);
            int ix1 = min(max((int)x0 + 1, 0), W - 1);
            float a  = __ldg(&r0[ix0]);
            float bb = __ldg(&r0[ix1]);
            float c  = __ldg(&r1[ix0]);
            float d  = __ldg(&r1[ix1]);
            float top = a * (1.f - wxs) + bb * wxs;
            float bot = c * (1.f - wxs) + d * wxs;
            float r = top * (1.f - wy) + bot * wy;
            bool inr = rowin && (sxf >= 0.f) && (sxf <= (float)(W - 1));
            res[ox] = inr ? r : 0.f;
        }
    }
    *o = make_float4(res[0], res[1], res[2], res[3]);
}

// ============================================================
extern "C" void kernel_launch(void* const* d_in, const int* in_sizes, int n_in,
                              void* d_out, int out_size) {
    const float* full = (const float*)d_in[0];
    const float* w1   = (const float*)d_in[1];
    const float* b1   = (const float*)d_in[2];
    const float* w2   = (const float*)d_in[3];
    const float* b2   = (const float*)d_in[4];
    float* out = (float*)d_out;

    static int smem_set = 0;
    if (!smem_set) {
        cudaFuncSetAttribute(k_fused, cudaFuncAttributeMaxDynamicSharedMemorySize,
                             SMEM_FUSED);
        smem_set = 1;
    }

    int n;
    k_resize2<<<dim3(HS / 8, BATCH), 256>>>(full);
    k_fused<<<dim3(WC / FTX, HC / FTY, BATCH), 256, SMEM_FUSED>>>(w1, b1, w2, b2);
    n = BATCH * HC * WC;  k_nms<<<(n + 255) / 256, 256>>>();
    k_topk_part<<<dim3(4, BATCH), 256>>>();
    k_topk_merge<<<BATCH, 32>>>(out);
    k_crop<<<dim3((CROPSZ * CROPSZ / 4 + 255) / 256, BATCH * KP), 256>>>(full, out);
}

// round 17
// speedup vs baseline: 1.1344x; 1.1344x over previous
#include <cuda_runtime.h>
#include <math.h>

#define BATCH 16
#define H     1024
#define W     1024
#define HS    512
#define WS    512
#define HC    256
#define WC    256
#define C1    32
#define KP    32
#define CROPSZ 160
#define NSL   32
#define SLICE 2048

// fused conv tile params
#define FTX 64
#define FTY 16
#define IMGW 144
#define SH1W 72
#define SH1SZ (20 * SH1W)

// ---- scratch (static __device__ per allocation rules) ----
__device__ float g_img[BATCH * HS * WS];             // 16 MB: resized 512x512
__device__ float g_cms[BATCH * HC * WC];             // 4 MB: confmaps
__device__ float g_nms[BATCH * HC * WC];             // 4 MB
__device__ unsigned long long g_pkey[BATCH * NSL * KP]; // per-slice top-32 keys
__device__ float g_cx[BATCH * KP];
__device__ float g_cy[BATCH * KP];
__device__ int   g_vld[BATCH * KP];

// output layout (flat concat, f32): crops | crop_offsets | centroid_vals | valid
#define OFF_OFFS  (BATCH * KP * CROPSZ * CROPSZ)
#define OFF_VALS  (OFF_OFFS + BATCH * KP * 2)
#define OFF_VALID (OFF_VALS + BATCH * KP)

// ============================================================
// 1) antialiased bilinear x0.5 resize — single pass, row-block.
// ============================================================
__global__ void __launch_bounds__(256) k_resize2(const float* __restrict__ in) {
    __shared__ float sht[18][512];
    int tid = threadIdx.x;
    int Y0  = blockIdx.x * 8;
    int b   = blockIdx.y;
    const float* ip = in + (size_t)b * H * W;
    int gy0 = 2 * Y0 - 1;

    for (int e = tid; e < 18 * 512; e += 256) {
        int r  = e >> 9;
        int xo = e & 511;
        int gy = gy0 + r;
        float v = 0.f;
        if (gy >= 0 && gy < H) {
            const float* row = ip + (size_t)gy * W;
            int base = 2 * xo - 1;
            float acc = 0.75f * row[base + 1] + 0.75f * row[base + 2];
            float wsum = 1.5f;
            if (base >= 0)    { acc += 0.25f * row[base];     wsum += 0.25f; }
            if (base + 3 < W) { acc += 0.25f * row[base + 3]; wsum += 0.25f; }
            v = acc / wsum;
        }
        sht[r][xo] = v;
    }
    __syncthreads();

    float* op = g_img + (size_t)b * HS * WS;
    for (int e = tid; e < 8 * 512; e += 256) {
        int yo = e >> 9;
        int xo = e & 511;
        int Y  = Y0 + yo;
        int lr = 2 * yo;
        float acc = 0.25f * sht[lr][xo]     + 0.75f * sht[lr + 1][xo]
                  + 0.75f * sht[lr + 2][xo] + 0.25f * sht[lr + 3][xo];
        float wsum = 2.f - 0.25f * ((Y == 0) + (Y == 511));
        op[(size_t)Y * WS + xo] = acc / wsum;
    }
}

// ============================================================
// 2) FUSED conv1 + conv2
// ============================================================
__device__ __forceinline__ unsigned long long pack2(float a, float b) {
    unsigned long long r;
    asm("mov.b64 %0, {%1, %2};" : "=l"(r) : "r"(__float_as_uint(a)), "r"(__float_as_uint(b)));
    return r;
}
__device__ __forceinline__ void unpack2(unsigned long long v, float& a, float& b) {
    unsigned int lo, hi;
    asm("mov.b64 {%0, %1}, %2;" : "=r"(lo), "=r"(hi) : "l"(v));
    a = __uint_as_float(lo); b = __uint_as_float(hi);
}
__device__ __forceinline__ void ffma2(unsigned long long& acc,
                                      unsigned long long v, unsigned long long w) {
    asm("fma.rn.f32x2 %0, %1, %2, %3;" : "=l"(acc) : "l"(v), "l"(w), "l"(acc));
}

#define SMEM_FUSED (400*8 + 32*4 + 800*4 + 43*IMGW*4 + 4*SH1SZ*4)

__global__ void __launch_bounds__(256) k_fused(const float* __restrict__ w1,
                                               const float* __restrict__ b1,
                                               const float* __restrict__ w2,
                                               const float* __restrict__ b2) {
    extern __shared__ unsigned char smraw[];
    unsigned long long* swp = (unsigned long long*)smraw;
    float* sbias = (float*)(swp + 400);
    float* sw2   = sbias + 32;
    float* simg  = sw2 + 800;
    float* sh1   = simg + 43 * IMGW;

    int tid  = threadIdx.x;
    int lane = tid & 31, wrow = tid >> 5;
    int x0 = blockIdx.x * FTX, y0 = blockIdx.y * FTY, b = blockIdx.z;

    if (tid < 200) {
        swp[tid]       = ((const unsigned long long*)w1)[tid];
        swp[200 + tid] = ((const unsigned long long*)w1)[200 + tid];
    }
    if (tid < 32) sbias[tid] = b1[tid];
    for (int e = tid; e < 800; e += 256) {
        int c = e / 25, t = e - c * 25;
        sw2[e] = w2[t * C1 + c];
    }

    const float* ip = g_img + (size_t)b * HS * WS;
    int iy0 = 2 * y0 - 5, ix0 = 2 * x0 - 5;
    for (int ly = wrow; ly < 43; ly += 8) {
        int gy = iy0 + ly;
        bool rok = (gy >= 0 && gy < HS);
        const float* prow = ip + (size_t)gy * WS;
        #pragma unroll
        for (int xc = 0; xc < 5; xc++) {
            int lx = lane + 32 * xc;
            if (xc == 4 && lane >= 11) continue;
            int gx = ix0 + lx;
            float v = 0.f;
            if (rok && gx >= 0 && gx < WS) v = prow[gx];
            simg[ly * IMGW + lx] = v;
        }
    }
    __syncthreads();

    int tx = tid & 15;
    int ty = tid >> 4;
    float acc2[4] = {0.f, 0.f, 0.f, 0.f};

    for (int cb = 0; cb < 8; cb++) {
        if (cb) __syncthreads();

        for (int e = tid; e < 20 * 68; e += 256) {
            int row = e / 68, col = e - row * 68;
            bool inb = ((unsigned)(y0 - 2 + row) < HC) &&
                       ((unsigned)(x0 - 2 + col) < WC);
            const float* pb = simg + (2 * row) * IMGW + 2 * col;
            float iv[25];
            #pragma unroll
            for (int ky = 0; ky < 5; ky++) {
                const float2* p2 = (const float2*)(pb + ky * IMGW);
                float2 a01 = p2[0];
                float2 a23 = p2[1];
                float  a4  = pb[ky * IMGW + 4];
                iv[ky * 5 + 0] = a01.x;
                iv[ky * 5 + 1] = a01.y;
                iv[ky * 5 + 2] = a23.x;
                iv[ky * 5 + 3] = a23.y;
                iv[ky * 5 + 4] = a4;
            }

            unsigned long long acc[2];
            #pragma unroll
            for (int j = 0; j < 2; j++)
                acc[j] = pack2(sbias[cb * 4 + 2 * j], sbias[cb * 4 + 2 * j + 1]);
            #pragma unroll
            for (int t = 0; t < 25; t++) {
                unsigned long long vv = pack2(iv[t], iv[t]);
                #pragma unroll
                for (int j = 0; j < 2; j++)
                    ffma2(acc[j], vv, swp[t * 16 + cb * 2 + j]);
            }
            int base = row * SH1W + col;
            #pragma unroll
            for (int j = 0; j < 2; j++) {
                float a, c2;
                unpack2(acc[j], a, c2);
                a  = inb ? fmaxf(a, 0.f)  : 0.f;
                c2 = inb ? fmaxf(c2, 0.f) : 0.f;
                sh1[(2 * j)     * SH1SZ + base] = a;
                sh1[(2 * j + 1) * SH1SZ + base] = c2;
            }
        }
        __syncthreads();

        #pragma unroll
        for (int c = 0; c < 4; c++) {
            const float* wp = sw2 + (cb * 4 + c) * 25;
            float wr[25];
            #pragma unroll
            for (int t = 0; t < 25; t++) wr[t] = wp[t];
            #pragma unroll
            for (int r = 0; r < 5; r++) {
                const float4* rp = (const float4*)(sh1 + c * SH1SZ + (ty + r) * SH1W);
                float4 va = rp[tx];
                float4 vb = rp[tx + 1];
                float v[8] = {va.x, va.y, va.z, va.w, vb.x, vb.y, vb.z, vb.w};
                #pragma unroll
                for (int kx = 0; kx < 5; kx++) {
                    float w = wr[r * 5 + kx];
                    #pragma unroll
                    for (int ox = 0; ox < 4; ox++)
                        acc2[ox] = fmaf(v[ox + kx], w, acc2[ox]);
                }
            }
        }
    }

    float bias2 = __ldg(b2);
    int gy = y0 + ty;
    #pragma unroll
    for (int ox = 0; ox < 4; ox++) {
        int gx = x0 + tx * 4 + ox;
        float z = acc2[ox] + bias2;
        g_cms[((size_t)b * HC + gy) * WC + gx] = 1.f / (1.f + expf(-z));
    }
}

// ============================================================
// 4a) 3x3 NMS + threshold -> global score buffer
// ============================================================
__global__ void __launch_bounds__(256) k_nms() {
    int i = blockIdx.x * blockDim.x + threadIdx.x;
    if (i >= BATCH * HC * WC) return;
    int p = i & (HC * WC - 1);
    int b = i >> 16;
    int y = p >> 8, x = p & 255;
    const float* cm = g_cms + (size_t)b * HC * WC;
    float v = cm[p];
    float mx = v;
    #pragma unroll
    for (int dy = -1; dy <= 1; dy++) {
        int yy = y + dy;
        if (yy < 0 || yy >= HC) continue;
        #pragma unroll
        for (int dx = -1; dx <= 1; dx++) {
            int xx = x + dx;
            if (xx < 0 || xx >= WC) continue;
            mx = fmaxf(mx, cm[yy * WC + xx]);
        }
    }
    g_nms[i] = (v >= mx && v > 0.2f) ? v : -INFINITY;
}

// ============================================================
// 4b) top-32 stage A: warp/slice, REDUX argmax + top-2 lane cache
// ============================================================
__device__ __forceinline__ unsigned int f2ord(float v) {
    unsigned int u = __float_as_uint(v);
    return (u & 0x80000000u) ? ~u : (u | 0x80000000u);
}
__device__ __forceinline__ float ord2f(unsigned int u) {
    unsigned int bits = (u & 0x80000000u) ? (u ^ 0x80000000u) : ~u;
    return __uint_as_float(bits);
}
__device__ __forceinline__ unsigned long long mk_key(float v, unsigned p) {
    return ((unsigned long long)f2ord(v) << 32) |
           (unsigned long long)(0xFFFFFFFFu - p);
}

__global__ void __launch_bounds__(32) k_topk_part() {
    int lane = threadIdx.x;
    int sl   = blockIdx.x;                  // slice 0..31
    int b    = blockIdx.y;
    float* nms = g_nms + (size_t)b * HC * WC;
    unsigned base = sl * SLICE;

    // per-lane top-2 over owned elements base + s*32 + lane
    unsigned long long k1 = 0, k2 = 0;
    #pragma unroll 8
    for (int s = 0; s < 64; s++) {
        unsigned p = base + s * 32 + lane;
        unsigned long long key = mk_key(nms[p], p);
        if (key > k1) { k2 = k1; k1 = key; }
        else if (key > k2) { k2 = key; }
    }

    unsigned long long* outk = g_pkey + (b * NSL + sl) * KP;

    for (int k = 0; k < KP; k++) {
        unsigned v1  = (unsigned)(k1 >> 32);
        unsigned w   = __reduce_max_sync(0xFFFFFFFFu, v1);
        unsigned myi = 0xFFFFFFFFu - (unsigned)k1;
        unsigned idc = (v1 == w) ? myi : 0xFFFFFFFFu;
        unsigned widx = __reduce_min_sync(0xFFFFFFFFu, idc);
        if (lane == 0)
            outk[k] = ((unsigned long long)w << 32) |
                      (unsigned long long)(0xFFFFFFFFu - widx);
        if (v1 == w && myi == widx) {       // unique owner (idx unique)
            nms[widx] = -INFINITY;          // tombstone for rescans
            k1 = k2; k2 = 0;
            if (k1 == 0) {                  // cache exhausted: rescan
                #pragma unroll 8
                for (int s = 0; s < 64; s++) {
                    unsigned p = base + s * 32 + lane;
                    unsigned long long key = mk_key(nms[p], p);
                    if (key > k1) { k2 = k1; k1 = key; }
                    else if (key > k2) { k2 = key; }
                }
            }
        }
    }
}

// ============================================================
// 4c) top-32 stage B: warp merge (REDUX) of 32x32 candidates + refine
// ============================================================
__global__ void __launch_bounds__(32) k_topk_merge(float* __restrict__ out) {
    int b    = blockIdx.x;
    int lane = threadIdx.x;         // 0..31

    // lane holds slot `lane` of each of the 32 slices (registers)
    unsigned long long cand[NSL];
    #pragma unroll
    for (int j = 0; j < NSL; j++)
        cand[j] = g_pkey[(b * NSL + j) * KP + lane];

    unsigned long long mybest = 0;
    #pragma unroll
    for (int j = 0; j < NSL; j++)
        if (cand[j] > mybest) mybest = cand[j];

    unsigned long long mywin = 0;
    for (int k = 0; k < KP; k++) {
        unsigned v1  = (unsigned)(mybest >> 32);
        unsigned w   = __reduce_max_sync(0xFFFFFFFFu, v1);
        unsigned myi = 0xFFFFFFFFu - (unsigned)mybest;
        unsigned idc = (v1 == w) ? myi : 0xFFFFFFFFu;
        unsigned widx = __reduce_min_sync(0xFFFFFFFFu, idc);
        unsigned long long wk = ((unsigned long long)w << 32) |
                                (unsigned long long)(0xFFFFFFFFu - widx);
        if (lane == k) mywin = wk;
        if (mybest == wk) {          // owner(s) of this exact key remove it
            unsigned long long nb = 0;
            #pragma unroll
            for (int j = 0; j < NSL; j++) {
                if (cand[j] == wk) cand[j] = 0;
                if (cand[j] > nb) nb = cand[j];
            }
            mybest = nb;
        }
    }

    // refine: lane k handles peak k
    int i = b * KP + lane;
    float vv = ord2f((unsigned int)(mywin >> 32));
    unsigned idx = 0xFFFFFFFFu - (unsigned int)(mywin & 0xFFFFFFFFu);
    int valid = isfinite(vv) ? 1 : 0;
    int py = (int)(idx >> 8), px = (int)(idx & 255);
    const float* cm = g_cms + (size_t)b * HC * WC;

    float gv = 1e-12f, sx = 0.f, sy = 0.f;
    #pragma unroll
    for (int dy = -2; dy <= 2; dy++) {
        int y = py + dy;
        if (y < 0 || y >= HC) continue;
        #pragma unroll
        for (int dx = -2; dx <= 2; dx++) {
            int x = px + dx;
            if (x < 0 || x >= WC) continue;
            float p = cm[y * WC + x];
            gv += p;
            sx += p * (float)dx;
            sy += p * (float)dy;
        }
    }
    float dxo = sx / gv, dyo = sy / gv;
    float cx = ((float)px + dxo) * 4.0f;
    float cy = ((float)py + dyo) * 4.0f;
    if (!valid) { cx = 80.f; cy = 80.f; }
    float cvv = valid ? vv : 0.f;

    g_cx[i] = cx; g_cy[i] = cy; g_vld[i] = valid;
    out[OFF_OFFS + i * 2 + 0] = cx - 80.f;
    out[OFF_OFFS + i * 2 + 1] = cy - 80.f;
    out[OFF_VALS + i] = cvv;
    out[OFF_VALID + i] = valid ? 1.f : 0.f;
}

// ============================================================
// 6) 160x160 bilinear crops: 4 outputs/thread, interior fast path
// ============================================================
__global__ void __launch_bounds__(256) k_crop(const float* __restrict__ img,
                                              float* __restrict__ out) {
    int bk = blockIdx.y;
    int q  = blockIdx.x * blockDim.x + threadIdx.x;
    if (q >= CROPSZ * CROPSZ / 4) return;
    float4* o = (float4*)(out + (size_t)bk * CROPSZ * CROPSZ) + q;
    if (!g_vld[bk]) { *o = make_float4(0.f, 0.f, 0.f, 0.f); return; }

    int b = bk / KP;
    float cx = g_cx[bk], cy = g_cy[bk];
    int pix = q * 4;
    int yy = pix / CROPSZ, xxb = pix % CROPSZ;

    float syf = cy - 79.5f + (float)yy;
    float y0 = floorf(syf);
    float wy = syf - y0;
    int iy0 = min(max((int)y0, 0), H - 1);
    int iy1 = min(max((int)y0 + 1, 0), H - 1);
    bool rowin = (syf >= 0.f) && (syf <= (float)(H - 1));
    const float* r0 = img + (size_t)b * H * W + (size_t)iy0 * W;
    const float* r1 = img + (size_t)b * H * W + (size_t)iy1 * W;

    float sxf0 = cx - 79.5f + (float)xxb;
    float x0f  = floorf(sxf0);
    float wx   = sxf0 - x0f;
    int x0i    = (int)x0f;

    float res[4];
    if (rowin && x0i >= 0 && x0i <= W - 5) {
        float c0 = __ldg(&r0[x0i]),     c1 = __ldg(&r0[x0i + 1]);
        float c2 = __ldg(&r0[x0i + 2]), c3 = __ldg(&r0[x0i + 3]);
        float c4 = __ldg(&r0[x0i + 4]);
        float d0 = __ldg(&r1[x0i]),     d1 = __ldg(&r1[x0i + 1]);
        float d2 = __ldg(&r1[x0i + 2]), d3 = __ldg(&r1[x0i + 3]);
        float d4 = __ldg(&r1[x0i + 4]);
        float iwx = 1.f - wx, iwy = 1.f - wy;
        float t0 = c0 * iwx + c1 * wx, t1 = c1 * iwx + c2 * wx;
        float t2 = c2 * iwx + c3 * wx, t3 = c3 * iwx + c4 * wx;
        float u0 = d0 * iwx + d1 * wx, u1 = d1 * iwx + d2 * wx;
        float u2 = d2 * iwx + d3 * wx, u3 = d3 * iwx + d4 * wx;
        res[0] = t0 * iwy + u0 * wy;
        res[1] = t1 * iwy + u1 * wy;
        res[2] = t2 * iwy + u2 * wy;
        res[3] = t3 * iwy + u3 * wy;
    } else {
        #pragma unroll
        for (int ox = 0; ox < 4; ox++) {
            float sxf = cx - 79.5f + (float)(xxb + ox);
            float x0 = floorf(sxf);
            float wxs = sxf - x0;
            int ix0 = min(max((int)x0, 0), W - 1);
            int ix1 = min(max((int)x0 + 1, 0), W - 1);
            float a  = __ldg(&r0[ix0]);
            float bb = __ldg(&r0[ix1]);
            float c  = __ldg(&r1[ix0]);
            float d  = __ldg(&r1[ix1]);
            float top = a * (1.f - wxs) + bb * wxs;
            float bot = c * (1.f - wxs) + d * wxs;
            float r = top * (1.f - wy) + bot * wy;
            bool inr = rowin && (sxf >= 0.f) && (sxf <= (float)(W - 1));
            res[ox] = inr ? r : 0.f;
        }
    }
    *o = make_float4(res[0], res[1], res[2], res[3]);
}

// ============================================================
extern "C" void kernel_launch(void* const* d_in, const int* in_sizes, int n_in,
                              void* d_out, int out_size) {
    const float* full = (const float*)d_in[0];
    const float* w1   = (const float*)d_in[1];
    const float* b1   = (const float*)d_in[2];
    const float* w2   = (const float*)d_in[3];
    const float* b2   = (const float*)d_in[4];
    float* out = (float*)d_out;

    static int smem_set = 0;
    if (!smem_set) {
        cudaFuncSetAttribute(k_fused, cudaFuncAttributeMaxDynamicSharedMemorySize,
                             SMEM_FUSED);
        smem_set = 1;
    }

    int n;
    k_resize2<<<dim3(HS / 8, BATCH), 256>>>(full);
    k_fused<<<dim3(WC / FTX, HC / FTY, BATCH), 256, SMEM_FUSED>>>(w1, b1, w2, b2);
    n = BATCH * HC * WC;  k_nms<<<(n + 255) / 256, 256>>>();
    k_topk_part<<<dim3(NSL, BATCH), 32>>>();
    k_topk_merge<<<BATCH, 32>>>(out);
    k_crop<<<dim3((CROPSZ * CROPSZ / 4 + 255) / 256, BATCH * KP), 256>>>(full, out);
}